// round 1
// baseline (speedup 1.0000x reference)
#include <cuda_runtime.h>
#include <math.h>

#define BB  4
#define NN  2048
#define FIN 256
#define DD  128
#define HH  4

// Scratch (device globals are the sanctioned scratch mechanism)
__device__ float g_Hx0 [BB*NN*DD];
__device__ float g_Hx  [BB*NN*DD];
__device__ float g_Kh  [HH*BB*NN*DD];
__device__ float g_Hout[BB*NN*DD];
__device__ float g_Xs  [BB*NN*DD];

// ---------------------------------------------------------------------------
// Generic tiled SGEMM: C[M,N] = A[M,K] @ B(K,N) (+bias), optional B-transposed
// (BT: B stored [N,K] row-major). 64x64 tile, BK=16, 256 threads, 4x4 micro.
// Batch: batchA = bz % modA, batchB = bz / divB, batchC = bz.
// ---------------------------------------------------------------------------
template<bool BT>
__global__ void __launch_bounds__(256)
sgemm_kernel(const float* __restrict__ A, long sA, int modA,
             const float* __restrict__ B, long sB, int divB,
             const float* __restrict__ bias,
             float* __restrict__ C, long sC,
             int M, int N, int K)
{
    __shared__ float As[16][68];
    __shared__ float Bs[16][68];

    int bz = blockIdx.z;
    A += (long)(bz % modA) * sA;
    B += (long)(bz / divB) * sB;
    C += (long)bz * sC;

    int n0 = blockIdx.x * 64;
    int m0 = blockIdx.y * 64;
    int t  = threadIdx.x;
    int ty = t >> 4, tx = t & 15;

    float acc[4][4] = {};

    int am  = t >> 2;            // 0..63
    int ak4 = (t & 3) * 4;       // 0,4,8,12
    int bkn, bn4;
    if (BT) { bkn = t >> 2; bn4 = (t & 3) * 4; }    // bkn = n row, bn4 = k
    else    { bkn = t >> 4; bn4 = (t & 15) * 4; }   // bkn = k row, bn4 = n

    for (int kt = 0; kt < K; kt += 16) {
        float4 av = *reinterpret_cast<const float4*>(A + (long)(m0 + am) * K + kt + ak4);
        As[ak4 + 0][am] = av.x; As[ak4 + 1][am] = av.y;
        As[ak4 + 2][am] = av.z; As[ak4 + 3][am] = av.w;
        if (BT) {
            float4 bv = *reinterpret_cast<const float4*>(B + (long)(n0 + bkn) * K + kt + bn4);
            Bs[bn4 + 0][bkn] = bv.x; Bs[bn4 + 1][bkn] = bv.y;
            Bs[bn4 + 2][bkn] = bv.z; Bs[bn4 + 3][bkn] = bv.w;
        } else {
            float4 bv = *reinterpret_cast<const float4*>(B + (long)(kt + bkn) * N + n0 + bn4);
            *reinterpret_cast<float4*>(&Bs[bkn][bn4]) = bv;
        }
        __syncthreads();
        #pragma unroll
        for (int k = 0; k < 16; k++) {
            float4 a = *reinterpret_cast<const float4*>(&As[k][ty * 4]);
            float4 b = *reinterpret_cast<const float4*>(&Bs[k][tx * 4]);
            float avr[4] = {a.x, a.y, a.z, a.w};
            float bvr[4] = {b.x, b.y, b.z, b.w};
            #pragma unroll
            for (int i = 0; i < 4; i++)
                #pragma unroll
                for (int j = 0; j < 4; j++)
                    acc[i][j] = fmaf(avr[i], bvr[j], acc[i][j]);
        }
        __syncthreads();
    }

    #pragma unroll
    for (int i = 0; i < 4; i++) {
        long row = m0 + ty * 4 + i;
        #pragma unroll
        for (int j = 0; j < 4; j++) {
            int col = n0 + tx * 4 + j;
            float v = acc[i][j];
            if (bias) v += bias[col];
            C[row * N + col] = v;
        }
    }
}

// ---------------------------------------------------------------------------
// Fused masked-tanh multi-head attention:
//   T[n,m] = sum_h tanh(A[n,m] * (Hx[n,:] . Kh[h][m,:]))
//   Hout   = relu(T @ Hx * (1/H))
// Block: 32 query rows x full D, streams m in 128-col tiles. 128 threads.
// Dynamic smem: Qt[128][32] | Kb[128*128] (K transposed, then V natural)
//               | Asx[32][128] | Ts[32][128]   = 112 KB
// ---------------------------------------------------------------------------
#define TN 32
#define TM 128

__device__ __forceinline__ float tanh_fast(float x) {
    asm("tanh.approx.f32 %0, %0;" : "+f"(x));
    return x;
}

__global__ void __launch_bounds__(128)
attn_kernel(const float* __restrict__ Aadj)
{
    extern __shared__ float smem[];
    float* Qt  = smem;                       // [d][r]  stride 32
    float* Kb  = Qt + 128 * 32;              // [d][c] (K) / [m][d] (V), stride 128
    float* Asx = Kb + 128 * 128;             // [r][c]  stride 128
    float* Ts  = Asx + 32 * 128;             // [r][c]  stride 128

    int b  = blockIdx.y;
    int n0 = blockIdx.x * TN;
    int t  = threadIdx.x;
    int ty = t >> 4;          // 0..7  -> rows ty*4..ty*4+3
    int tx = t & 15;          // 0..15 -> cols {4tx..4tx+3} U {64+4tx..64+4tx+3}

    const float* Hxb = g_Hx + (long)b * NN * DD;
    const float* Ab  = Aadj + (long)b * NN * NN;

    // Load Q transposed: Qt[d][r]
    {
        int r = t & 31, dgb = t >> 5;
        #pragma unroll
        for (int i = 0; i < 8; i++) {
            int d4 = (dgb + 4 * i) * 4;
            float4 v = *reinterpret_cast<const float4*>(Hxb + (long)(n0 + r) * DD + d4);
            Qt[(d4 + 0) * 32 + r] = v.x; Qt[(d4 + 1) * 32 + r] = v.y;
            Qt[(d4 + 2) * 32 + r] = v.z; Qt[(d4 + 3) * 32 + r] = v.w;
        }
    }

    float hacc[4][8] = {};   // persistent Hout accumulators

    for (int m0 = 0; m0 < NN; m0 += TM) {
        float tacc[4][8] = {};

        for (int h = 0; h < HH; h++) {
            __syncthreads();  // prior readers of Kb/Asx/Ts done
            if (h == 0) {
                #pragma unroll
                for (int i = 0; i < 32; i++)
                    Asx[i * 128 + t] = Ab[(long)(n0 + i) * NN + m0 + t];
            }
            // Load Kh tile transposed: Kb[d][c], thread owns column c=t
            {
                const float* Khp = g_Kh + ((long)h * BB + b) * (long)NN * DD + (long)m0 * DD;
                const float* row = Khp + (long)t * DD;
                #pragma unroll
                for (int i = 0; i < 32; i++) {
                    float4 v = *reinterpret_cast<const float4*>(row + i * 4);
                    Kb[(i * 4 + 0) * 128 + t] = v.x; Kb[(i * 4 + 1) * 128 + t] = v.y;
                    Kb[(i * 4 + 2) * 128 + t] = v.z; Kb[(i * 4 + 3) * 128 + t] = v.w;
                }
            }
            __syncthreads();

            float sacc[4][8] = {};
            #pragma unroll 8
            for (int d = 0; d < 128; d++) {
                float4 qa = *reinterpret_cast<const float4*>(&Qt[d * 32 + ty * 4]);
                float4 k0 = *reinterpret_cast<const float4*>(&Kb[d * 128 + tx * 4]);
                float4 k1 = *reinterpret_cast<const float4*>(&Kb[d * 128 + 64 + tx * 4]);
                float qv[4] = {qa.x, qa.y, qa.z, qa.w};
                float kv[8] = {k0.x, k0.y, k0.z, k0.w, k1.x, k1.y, k1.z, k1.w};
                #pragma unroll
                for (int i = 0; i < 4; i++)
                    #pragma unroll
                    for (int j = 0; j < 8; j++)
                        sacc[i][j] = fmaf(qv[i], kv[j], sacc[i][j]);
            }
            #pragma unroll
            for (int i = 0; i < 4; i++) {
                int r = ty * 4 + i;
                #pragma unroll
                for (int j = 0; j < 8; j++) {
                    int c = (j < 4) ? (tx * 4 + j) : (64 + tx * 4 + (j - 4));
                    tacc[i][j] += tanh_fast(Asx[r * 128 + c] * sacc[i][j]);
                }
            }
        }

        __syncthreads();  // S-phase reads of Kb done; safe to overwrite with V
        #pragma unroll
        for (int i = 0; i < 4; i++) {
            int r = ty * 4 + i;
            #pragma unroll
            for (int j = 0; j < 8; j++) {
                int c = (j < 4) ? (tx * 4 + j) : (64 + tx * 4 + (j - 4));
                Ts[r * 128 + c] = tacc[i][j];
            }
        }
        // Load V tile (natural [m][d]) into Kb
        {
            int c4 = (t & 31) * 4, w = t >> 5;
            #pragma unroll
            for (int i = 0; i < 32; i++) {
                int m = 4 * i + w;
                *reinterpret_cast<float4*>(&Kb[m * 128 + c4]) =
                    *reinterpret_cast<const float4*>(Hxb + (long)(m0 + m) * DD + c4);
            }
        }
        __syncthreads();

        #pragma unroll 4
        for (int m = 0; m < TM; m++) {
            float tv[4];
            #pragma unroll
            for (int i = 0; i < 4; i++) tv[i] = Ts[(ty * 4 + i) * 128 + m];
            float4 v0 = *reinterpret_cast<const float4*>(&Kb[m * 128 + tx * 4]);
            float4 v1 = *reinterpret_cast<const float4*>(&Kb[m * 128 + 64 + tx * 4]);
            float vv[8] = {v0.x, v0.y, v0.z, v0.w, v1.x, v1.y, v1.z, v1.w};
            #pragma unroll
            for (int i = 0; i < 4; i++)
                #pragma unroll
                for (int j = 0; j < 8; j++)
                    hacc[i][j] = fmaf(tv[i], vv[j], hacc[i][j]);
        }
    }

    float* Ho = g_Hout + (long)b * NN * DD;
    #pragma unroll
    for (int i = 0; i < 4; i++) {
        long r = n0 + ty * 4 + i;
        #pragma unroll
        for (int j = 0; j < 8; j++) {
            int c = (j < 4) ? (tx * 4 + j) : (64 + tx * 4 + (j - 4));
            Ho[r * DD + c] = fmaxf(hacc[i][j] * (1.0f / HH), 0.0f);
        }
    }
}

// ---------------------------------------------------------------------------
// Gate: z = sigmoid(Hout@W_u + Xs@W_x + b_u + b_x + update_bias)
//       out = Hout*z + Xs*(1-z).  16 rows/block, 256 threads.
// ---------------------------------------------------------------------------
__global__ void __launch_bounds__(256)
gate_kernel(const float* __restrict__ Wu, const float* __restrict__ bu,
            const float* __restrict__ Wx, const float* __restrict__ bx,
            const float* __restrict__ ub, float* __restrict__ out)
{
    __shared__ float sH[16][128];
    __shared__ float sX[16][128];
    int r0 = blockIdx.x * 16;
    int t  = threadIdx.x;

    for (int i = t; i < 16 * 128; i += 256) {
        int r = i >> 7, c = i & 127;
        sH[r][c] = g_Hout[(long)(r0 + r) * DD + c];
        sX[r][c] = g_Xs  [(long)(r0 + r) * DD + c];
    }
    __syncthreads();

    int ty = t >> 4;        // row 0..15
    int tx = t & 15;        // col block of 8: tx*8..tx*8+7
    float acc[8] = {};
    for (int k = 0; k < 128; k++) {
        float h = sH[ty][k], x = sX[ty][k];
        const float4* wu4 = reinterpret_cast<const float4*>(Wu + k * DD + tx * 8);
        const float4* wx4 = reinterpret_cast<const float4*>(Wx + k * DD + tx * 8);
        float4 u0 = wu4[0], u1 = wu4[1];
        float4 w0 = wx4[0], w1 = wx4[1];
        acc[0] = fmaf(h, u0.x, fmaf(x, w0.x, acc[0]));
        acc[1] = fmaf(h, u0.y, fmaf(x, w0.y, acc[1]));
        acc[2] = fmaf(h, u0.z, fmaf(x, w0.z, acc[2]));
        acc[3] = fmaf(h, u0.w, fmaf(x, w0.w, acc[3]));
        acc[4] = fmaf(h, u1.x, fmaf(x, w1.x, acc[4]));
        acc[5] = fmaf(h, u1.y, fmaf(x, w1.y, acc[5]));
        acc[6] = fmaf(h, u1.z, fmaf(x, w1.z, acc[6]));
        acc[7] = fmaf(h, u1.w, fmaf(x, w1.w, acc[7]));
    }
    #pragma unroll
    for (int j = 0; j < 8; j++) {
        int c = tx * 8 + j;
        float zlin = acc[j] + bu[c] + bx[c] + ub[c];
        float z = 1.0f / (1.0f + expf(-zlin));
        float hv = sH[ty][c], xv = sX[ty][c];
        out[(long)(r0 + ty) * DD + c] = hv * z + xv * (1.0f - z);
    }
}

__global__ void copyA_kernel(const float4* __restrict__ src, float4* __restrict__ dst, long n4)
{
    long i = blockIdx.x * (long)blockDim.x + threadIdx.x;
    long stride = (long)gridDim.x * blockDim.x;
    for (; i < n4; i += stride) dst[i] = src[i];
}

// ---------------------------------------------------------------------------
extern "C" void kernel_launch(void* const* d_in, const int* in_sizes, int n_in,
                              void* d_out, int out_size)
{
    const float* X      = (const float*)d_in[0];
    const float* Aadj   = (const float*)d_in[1];
    const float* kernW  = (const float*)d_in[2];
    const float* bias   = (const float*)d_in[3];
    const float* ubias  = (const float*)d_in[4];
    const float* attn   = (const float*)d_in[5];
    const float* W_skip = (const float*)d_in[6];
    const float* b_skip = (const float*)d_in[7];
    const float* W_u    = (const float*)d_in[8];
    const float* b_u    = (const float*)d_in[9];
    const float* W_x    = (const float*)d_in[10];
    const float* b_x    = (const float*)d_in[11];
    float* out = (float*)d_out;

    float *Hx0, *Hx, *Kh, *Xs;
    cudaGetSymbolAddress((void**)&Hx0, g_Hx0);
    cudaGetSymbolAddress((void**)&Hx,  g_Hx);
    cudaGetSymbolAddress((void**)&Kh,  g_Kh);
    cudaGetSymbolAddress((void**)&Xs,  g_Xs);

    // Stage 1: Hx0 = X @ kernel + bias   [8192,256]@[256,128]
    sgemm_kernel<false><<<dim3(2, 128, 1), 256>>>(
        X, 0, 1, kernW, 0, 1, bias, Hx0, 0, BB * NN, DD, FIN);

    // Stage 2: Hx[b] = A[b] @ Hx0[b]     [2048,2048]@[2048,128] x4
    sgemm_kernel<false><<<dim3(2, 32, 4), 256>>>(
        Aadj, (long)NN * NN, 4, Hx0, (long)NN * DD, 1, nullptr,
        Hx, (long)NN * DD, NN, DD, NN);

    // Stage 3: Kh[h*B+b] = Hx[b] @ attn[h]^T   [2048,128]@[128,128]^T x16
    sgemm_kernel<true><<<dim3(2, 32, 16), 256>>>(
        Hx, (long)NN * DD, 4, attn, (long)DD * DD, 4, nullptr,
        Kh, (long)NN * DD, NN, DD, DD);

    // Stage 5: Xs = X @ W_skip + b_skip
    sgemm_kernel<false><<<dim3(2, 128, 1), 256>>>(
        X, 0, 1, W_skip, 0, 1, b_skip, Xs, 0, BB * NN, DD, FIN);

    // Stage 4: fused masked-tanh attention -> g_Hout
    const int ATTN_SMEM = (128 * 32 + 128 * 128 + 32 * 128 + 32 * 128) * 4; // 112 KB
    cudaFuncSetAttribute(attn_kernel, cudaFuncAttributeMaxDynamicSharedMemorySize, ATTN_SMEM);
    attn_kernel<<<dim3(NN / TN, BB), 128, ATTN_SMEM>>>(Aadj);

    // Stage 6: gated skip -> out[0 : B*N*D]
    gate_kernel<<<BB * NN / 16, 256>>>(W_u, b_u, W_x, b_x, ubias, out);

    // Stage 7: second tuple element: copy A after out
    copyA_kernel<<<1024, 256>>>((const float4*)Aadj,
                                (float4*)(out + (long)BB * NN * DD),
                                (long)BB * NN * NN / 4);
}

// round 2
// speedup vs baseline: 1.0003x; 1.0003x over previous
#include <cuda_runtime.h>
#include <math.h>

#define BB  4
#define NN  2048
#define FIN 256
#define DD  128
#define HH  4

// Scratch (device globals are the sanctioned scratch mechanism)
__device__ float g_Hx0 [BB*NN*DD];
__device__ float g_Hx  [BB*NN*DD];
__device__ float g_Kh  [HH*BB*NN*DD];
__device__ float g_Hout[BB*NN*DD];
__device__ float g_Xs  [BB*NN*DD];

// ---------------------------------------------------------------------------
// Generic tiled SGEMM: C[M,N] = A[M,K] @ B(K,N) (+bias), optional B-transposed
// (BT: B stored [N,K] row-major). 64x64 tile, BK=16, 256 threads, 4x4 micro.
// Batch: batchA = bz % modA, batchB = bz / divB, batchC = bz.
// ---------------------------------------------------------------------------
template<bool BT>
__global__ void __launch_bounds__(256)
sgemm_kernel(const float* __restrict__ A, long sA, int modA,
             const float* __restrict__ B, long sB, int divB,
             const float* __restrict__ bias,
             float* __restrict__ C, long sC,
             int M, int N, int K)
{
    __shared__ float As[16][68];
    __shared__ float Bs[16][68];

    int bz = blockIdx.z;
    A += (long)(bz % modA) * sA;
    B += (long)(bz / divB) * sB;
    C += (long)bz * sC;

    int n0 = blockIdx.x * 64;
    int m0 = blockIdx.y * 64;
    int t  = threadIdx.x;
    int ty = t >> 4, tx = t & 15;

    float acc[4][4] = {};

    int am  = t >> 2;            // 0..63
    int ak4 = (t & 3) * 4;       // 0,4,8,12
    int bkn, bn4;
    if (BT) { bkn = t >> 2; bn4 = (t & 3) * 4; }    // bkn = n row, bn4 = k
    else    { bkn = t >> 4; bn4 = (t & 15) * 4; }   // bkn = k row, bn4 = n

    for (int kt = 0; kt < K; kt += 16) {
        float4 av = *reinterpret_cast<const float4*>(A + (long)(m0 + am) * K + kt + ak4);
        As[ak4 + 0][am] = av.x; As[ak4 + 1][am] = av.y;
        As[ak4 + 2][am] = av.z; As[ak4 + 3][am] = av.w;
        if (BT) {
            float4 bv = *reinterpret_cast<const float4*>(B + (long)(n0 + bkn) * K + kt + bn4);
            Bs[bn4 + 0][bkn] = bv.x; Bs[bn4 + 1][bkn] = bv.y;
            Bs[bn4 + 2][bkn] = bv.z; Bs[bn4 + 3][bkn] = bv.w;
        } else {
            float4 bv = *reinterpret_cast<const float4*>(B + (long)(kt + bkn) * N + n0 + bn4);
            *reinterpret_cast<float4*>(&Bs[bkn][bn4]) = bv;
        }
        __syncthreads();
        #pragma unroll
        for (int k = 0; k < 16; k++) {
            float4 a = *reinterpret_cast<const float4*>(&As[k][ty * 4]);
            float4 b = *reinterpret_cast<const float4*>(&Bs[k][tx * 4]);
            float avr[4] = {a.x, a.y, a.z, a.w};
            float bvr[4] = {b.x, b.y, b.z, b.w};
            #pragma unroll
            for (int i = 0; i < 4; i++)
                #pragma unroll
                for (int j = 0; j < 4; j++)
                    acc[i][j] = fmaf(avr[i], bvr[j], acc[i][j]);
        }
        __syncthreads();
    }

    #pragma unroll
    for (int i = 0; i < 4; i++) {
        long row = m0 + ty * 4 + i;
        #pragma unroll
        for (int j = 0; j < 4; j++) {
            int col = n0 + tx * 4 + j;
            float v = acc[i][j];
            if (bias) v += bias[col];
            C[row * N + col] = v;
        }
    }
}

// ---------------------------------------------------------------------------
// Fused masked-tanh multi-head attention:
//   T[n,m] = sum_h tanh(A[n,m] * (Hx[n,:] . Kh[h][m,:]))
//   Hout   = relu(T @ Hx * (1/H))
// Block: 32 query rows x full D, streams m in 128-col tiles. 128 threads.
// Dynamic smem: Qt[128][32] | Kb[128*128] (K transposed, then V natural)
//               | Asx[32][128] | Ts[32][128]   = 112 KB
// ---------------------------------------------------------------------------
#define TN 32
#define TM 128

__device__ __forceinline__ float tanh_fast(float x) {
    asm("tanh.approx.f32 %0, %0;" : "+f"(x));
    return x;
}

__global__ void __launch_bounds__(128)
attn_kernel(const float* __restrict__ Aadj)
{
    extern __shared__ float smem[];
    float* Qt  = smem;                       // [d][r]  stride 32
    float* Kb  = Qt + 128 * 32;              // [d][c] (K) / [m][d] (V), stride 128
    float* Asx = Kb + 128 * 128;             // [r][c]  stride 128
    float* Ts  = Asx + 32 * 128;             // [r][c]  stride 128

    int b  = blockIdx.y;
    int n0 = blockIdx.x * TN;
    int t  = threadIdx.x;
    int ty = t >> 4;          // 0..7  -> rows ty*4..ty*4+3
    int tx = t & 15;          // 0..15 -> cols {4tx..4tx+3} U {64+4tx..64+4tx+3}

    const float* Hxb = g_Hx + (long)b * NN * DD;
    const float* Ab  = Aadj + (long)b * NN * NN;

    // Load Q transposed: Qt[d][r]
    {
        int r = t & 31, dgb = t >> 5;
        #pragma unroll
        for (int i = 0; i < 8; i++) {
            int d4 = (dgb + 4 * i) * 4;
            float4 v = *reinterpret_cast<const float4*>(Hxb + (long)(n0 + r) * DD + d4);
            Qt[(d4 + 0) * 32 + r] = v.x; Qt[(d4 + 1) * 32 + r] = v.y;
            Qt[(d4 + 2) * 32 + r] = v.z; Qt[(d4 + 3) * 32 + r] = v.w;
        }
    }

    float hacc[4][8] = {};   // persistent Hout accumulators

    for (int m0 = 0; m0 < NN; m0 += TM) {
        float tacc[4][8] = {};

        for (int h = 0; h < HH; h++) {
            __syncthreads();  // prior readers of Kb/Asx/Ts done
            if (h == 0) {
                #pragma unroll
                for (int i = 0; i < 32; i++)
                    Asx[i * 128 + t] = Ab[(long)(n0 + i) * NN + m0 + t];
            }
            // Load Kh tile transposed: Kb[d][c], thread owns column c=t
            {
                const float* Khp = g_Kh + ((long)h * BB + b) * (long)NN * DD + (long)m0 * DD;
                const float* row = Khp + (long)t * DD;
                #pragma unroll
                for (int i = 0; i < 32; i++) {
                    float4 v = *reinterpret_cast<const float4*>(row + i * 4);
                    Kb[(i * 4 + 0) * 128 + t] = v.x; Kb[(i * 4 + 1) * 128 + t] = v.y;
                    Kb[(i * 4 + 2) * 128 + t] = v.z; Kb[(i * 4 + 3) * 128 + t] = v.w;
                }
            }
            __syncthreads();

            float sacc[4][8] = {};
            #pragma unroll 8
            for (int d = 0; d < 128; d++) {
                float4 qa = *reinterpret_cast<const float4*>(&Qt[d * 32 + ty * 4]);
                float4 k0 = *reinterpret_cast<const float4*>(&Kb[d * 128 + tx * 4]);
                float4 k1 = *reinterpret_cast<const float4*>(&Kb[d * 128 + 64 + tx * 4]);
                float qv[4] = {qa.x, qa.y, qa.z, qa.w};
                float kv[8] = {k0.x, k0.y, k0.z, k0.w, k1.x, k1.y, k1.z, k1.w};
                #pragma unroll
                for (int i = 0; i < 4; i++)
                    #pragma unroll
                    for (int j = 0; j < 8; j++)
                        sacc[i][j] = fmaf(qv[i], kv[j], sacc[i][j]);
            }
            #pragma unroll
            for (int i = 0; i < 4; i++) {
                int r = ty * 4 + i;
                #pragma unroll
                for (int j = 0; j < 8; j++) {
                    int c = (j < 4) ? (tx * 4 + j) : (64 + tx * 4 + (j - 4));
                    tacc[i][j] += tanh_fast(Asx[r * 128 + c] * sacc[i][j]);
                }
            }
        }

        __syncthreads();  // S-phase reads of Kb done; safe to overwrite with V
        #pragma unroll
        for (int i = 0; i < 4; i++) {
            int r = ty * 4 + i;
            #pragma unroll
            for (int j = 0; j < 8; j++) {
                int c = (j < 4) ? (tx * 4 + j) : (64 + tx * 4 + (j - 4));
                Ts[r * 128 + c] = tacc[i][j];
            }
        }
        // Load V tile (natural [m][d]) into Kb
        {
            int c4 = (t & 31) * 4, w = t >> 5;
            #pragma unroll
            for (int i = 0; i < 32; i++) {
                int m = 4 * i + w;
                *reinterpret_cast<float4*>(&Kb[m * 128 + c4]) =
                    *reinterpret_cast<const float4*>(Hxb + (long)(m0 + m) * DD + c4);
            }
        }
        __syncthreads();

        #pragma unroll 4
        for (int m = 0; m < TM; m++) {
            float tv[4];
            #pragma unroll
            for (int i = 0; i < 4; i++) tv[i] = Ts[(ty * 4 + i) * 128 + m];
            float4 v0 = *reinterpret_cast<const float4*>(&Kb[m * 128 + tx * 4]);
            float4 v1 = *reinterpret_cast<const float4*>(&Kb[m * 128 + 64 + tx * 4]);
            float vv[8] = {v0.x, v0.y, v0.z, v0.w, v1.x, v1.y, v1.z, v1.w};
            #pragma unroll
            for (int i = 0; i < 4; i++)
                #pragma unroll
                for (int j = 0; j < 8; j++)
                    hacc[i][j] = fmaf(tv[i], vv[j], hacc[i][j]);
        }
    }

    float* Ho = g_Hout + (long)b * NN * DD;
    #pragma unroll
    for (int i = 0; i < 4; i++) {
        long r = n0 + ty * 4 + i;
        #pragma unroll
        for (int j = 0; j < 8; j++) {
            int c = (j < 4) ? (tx * 4 + j) : (64 + tx * 4 + (j - 4));
            Ho[r * DD + c] = fmaxf(hacc[i][j] * (1.0f / HH), 0.0f);
        }
    }
}

// ---------------------------------------------------------------------------
// Gate: z = sigmoid(Hout@W_u + Xs@W_x + b_u + b_x + update_bias)
//       out = Hout*z + Xs*(1-z).  16 rows/block, 256 threads.
// ---------------------------------------------------------------------------
__global__ void __launch_bounds__(256)
gate_kernel(const float* __restrict__ Wu, const float* __restrict__ bu,
            const float* __restrict__ Wx, const float* __restrict__ bx,
            const float* __restrict__ ub, float* __restrict__ out)
{
    __shared__ float sH[16][128];
    __shared__ float sX[16][128];
    int r0 = blockIdx.x * 16;
    int t  = threadIdx.x;

    for (int i = t; i < 16 * 128; i += 256) {
        int r = i >> 7, c = i & 127;
        sH[r][c] = g_Hout[(long)(r0 + r) * DD + c];
        sX[r][c] = g_Xs  [(long)(r0 + r) * DD + c];
    }
    __syncthreads();

    int ty = t >> 4;        // row 0..15
    int tx = t & 15;        // col block of 8: tx*8..tx*8+7
    float acc[8] = {};
    for (int k = 0; k < 128; k++) {
        float h = sH[ty][k], x = sX[ty][k];
        const float4* wu4 = reinterpret_cast<const float4*>(Wu + k * DD + tx * 8);
        const float4* wx4 = reinterpret_cast<const float4*>(Wx + k * DD + tx * 8);
        float4 u0 = wu4[0], u1 = wu4[1];
        float4 w0 = wx4[0], w1 = wx4[1];
        acc[0] = fmaf(h, u0.x, fmaf(x, w0.x, acc[0]));
        acc[1] = fmaf(h, u0.y, fmaf(x, w0.y, acc[1]));
        acc[2] = fmaf(h, u0.z, fmaf(x, w0.z, acc[2]));
        acc[3] = fmaf(h, u0.w, fmaf(x, w0.w, acc[3]));
        acc[4] = fmaf(h, u1.x, fmaf(x, w1.x, acc[4]));
        acc[5] = fmaf(h, u1.y, fmaf(x, w1.y, acc[5]));
        acc[6] = fmaf(h, u1.z, fmaf(x, w1.z, acc[6]));
        acc[7] = fmaf(h, u1.w, fmaf(x, w1.w, acc[7]));
    }
    #pragma unroll
    for (int j = 0; j < 8; j++) {
        int c = tx * 8 + j;
        float zlin = acc[j] + bu[c] + bx[c] + ub[c];
        float z = 1.0f / (1.0f + expf(-zlin));
        float hv = sH[ty][c], xv = sX[ty][c];
        out[(long)(r0 + ty) * DD + c] = hv * z + xv * (1.0f - z);
    }
}

__global__ void copyA_kernel(const float4* __restrict__ src, float4* __restrict__ dst, long n4)
{
    long i = blockIdx.x * (long)blockDim.x + threadIdx.x;
    long stride = (long)gridDim.x * blockDim.x;
    for (; i < n4; i += stride) dst[i] = src[i];
}

// ---------------------------------------------------------------------------
extern "C" void kernel_launch(void* const* d_in, const int* in_sizes, int n_in,
                              void* d_out, int out_size)
{
    const float* X      = (const float*)d_in[0];
    const float* Aadj   = (const float*)d_in[1];
    const float* kernW  = (const float*)d_in[2];
    const float* bias   = (const float*)d_in[3];
    const float* ubias  = (const float*)d_in[4];
    const float* attn   = (const float*)d_in[5];
    const float* W_skip = (const float*)d_in[6];
    const float* b_skip = (const float*)d_in[7];
    const float* W_u    = (const float*)d_in[8];
    const float* b_u    = (const float*)d_in[9];
    const float* W_x    = (const float*)d_in[10];
    const float* b_x    = (const float*)d_in[11];
    float* out = (float*)d_out;

    float *Hx0, *Hx, *Kh, *Xs;
    cudaGetSymbolAddress((void**)&Hx0, g_Hx0);
    cudaGetSymbolAddress((void**)&Hx,  g_Hx);
    cudaGetSymbolAddress((void**)&Kh,  g_Kh);
    cudaGetSymbolAddress((void**)&Xs,  g_Xs);

    // Stage 1: Hx0 = X @ kernel + bias   [8192,256]@[256,128]
    sgemm_kernel<false><<<dim3(2, 128, 1), 256>>>(
        X, 0, 1, kernW, 0, 1, bias, Hx0, 0, BB * NN, DD, FIN);

    // Stage 2: Hx[b] = A[b] @ Hx0[b]     [2048,2048]@[2048,128] x4
    sgemm_kernel<false><<<dim3(2, 32, 4), 256>>>(
        Aadj, (long)NN * NN, 4, Hx0, (long)NN * DD, 1, nullptr,
        Hx, (long)NN * DD, NN, DD, NN);

    // Stage 3: Kh[h*B+b] = Hx[b] @ attn[h]^T   [2048,128]@[128,128]^T x16
    sgemm_kernel<true><<<dim3(2, 32, 16), 256>>>(
        Hx, (long)NN * DD, 4, attn, (long)DD * DD, 4, nullptr,
        Kh, (long)NN * DD, NN, DD, DD);

    // Stage 5: Xs = X @ W_skip + b_skip
    sgemm_kernel<false><<<dim3(2, 128, 1), 256>>>(
        X, 0, 1, W_skip, 0, 1, b_skip, Xs, 0, BB * NN, DD, FIN);

    // Stage 4: fused masked-tanh attention -> g_Hout
    const int ATTN_SMEM = (128 * 32 + 128 * 128 + 32 * 128 + 32 * 128) * 4; // 112 KB
    cudaFuncSetAttribute(attn_kernel, cudaFuncAttributeMaxDynamicSharedMemorySize, ATTN_SMEM);
    attn_kernel<<<dim3(NN / TN, BB), 128, ATTN_SMEM>>>(Aadj);

    // Stage 6: gated skip -> out[0 : B*N*D]
    gate_kernel<<<BB * NN / 16, 256>>>(W_u, b_u, W_x, b_x, ubias, out);

    // Stage 7: second tuple element: copy A after out
    copyA_kernel<<<1024, 256>>>((const float4*)Aadj,
                                (float4*)(out + (long)BB * NN * DD),
                                (long)BB * NN * NN / 4);
}

// round 3
// speedup vs baseline: 1.0003x; 1.0000x over previous
#include <cuda_runtime.h>
#include <math.h>

#define BB  4
#define NN  2048
#define FIN 256
#define DD  128
#define HH  4

// Scratch (device globals are the sanctioned scratch mechanism)
__device__ float g_Hx0 [BB*NN*DD];
__device__ float g_Hx  [BB*NN*DD];
__device__ float g_Kh  [HH*BB*NN*DD];
__device__ float g_Hout[BB*NN*DD];
__device__ float g_Xs  [BB*NN*DD];

// ---------------------------------------------------------------------------
// Generic tiled SGEMM: C[M,N] = A[M,K] @ B(K,N) (+bias), optional B-transposed
// (BT: B stored [N,K] row-major). 64x64 tile, BK=16, 256 threads, 4x4 micro.
// Batch: batchA = bz % modA, batchB = bz / divB, batchC = bz.
// ---------------------------------------------------------------------------
template<bool BT>
__global__ void __launch_bounds__(256)
sgemm_kernel(const float* __restrict__ A, long sA, int modA,
             const float* __restrict__ B, long sB, int divB,
             const float* __restrict__ bias,
             float* __restrict__ C, long sC,
             int M, int N, int K)
{
    __shared__ float As[16][68];
    __shared__ float Bs[16][68];

    int bz = blockIdx.z;
    A += (long)(bz % modA) * sA;
    B += (long)(bz / divB) * sB;
    C += (long)bz * sC;

    int n0 = blockIdx.x * 64;
    int m0 = blockIdx.y * 64;
    int t  = threadIdx.x;
    int ty = t >> 4, tx = t & 15;

    float acc[4][4] = {};

    int am  = t >> 2;            // 0..63
    int ak4 = (t & 3) * 4;       // 0,4,8,12
    int bkn, bn4;
    if (BT) { bkn = t >> 2; bn4 = (t & 3) * 4; }    // bkn = n row, bn4 = k
    else    { bkn = t >> 4; bn4 = (t & 15) * 4; }   // bkn = k row, bn4 = n

    for (int kt = 0; kt < K; kt += 16) {
        float4 av = *reinterpret_cast<const float4*>(A + (long)(m0 + am) * K + kt + ak4);
        As[ak4 + 0][am] = av.x; As[ak4 + 1][am] = av.y;
        As[ak4 + 2][am] = av.z; As[ak4 + 3][am] = av.w;
        if (BT) {
            float4 bv = *reinterpret_cast<const float4*>(B + (long)(n0 + bkn) * K + kt + bn4);
            Bs[bn4 + 0][bkn] = bv.x; Bs[bn4 + 1][bkn] = bv.y;
            Bs[bn4 + 2][bkn] = bv.z; Bs[bn4 + 3][bkn] = bv.w;
        } else {
            float4 bv = *reinterpret_cast<const float4*>(B + (long)(kt + bkn) * N + n0 + bn4);
            *reinterpret_cast<float4*>(&Bs[bkn][bn4]) = bv;
        }
        __syncthreads();
        #pragma unroll
        for (int k = 0; k < 16; k++) {
            float4 a = *reinterpret_cast<const float4*>(&As[k][ty * 4]);
            float4 b = *reinterpret_cast<const float4*>(&Bs[k][tx * 4]);
            float avr[4] = {a.x, a.y, a.z, a.w};
            float bvr[4] = {b.x, b.y, b.z, b.w};
            #pragma unroll
            for (int i = 0; i < 4; i++)
                #pragma unroll
                for (int j = 0; j < 4; j++)
                    acc[i][j] = fmaf(avr[i], bvr[j], acc[i][j]);
        }
        __syncthreads();
    }

    #pragma unroll
    for (int i = 0; i < 4; i++) {
        long row = m0 + ty * 4 + i;
        #pragma unroll
        for (int j = 0; j < 4; j++) {
            int col = n0 + tx * 4 + j;
            float v = acc[i][j];
            if (bias) v += bias[col];
            C[row * N + col] = v;
        }
    }
}

// ---------------------------------------------------------------------------
// Fused masked-tanh multi-head attention:
//   T[n,m] = sum_h tanh(A[n,m] * (Hx[n,:] . Kh[h][m,:]))
//   Hout   = relu(T @ Hx * (1/H))
// Block: 32 query rows x full D, streams m in 128-col tiles. 128 threads.
// Dynamic smem: Qt[128][32] | Kb[128*128] (K transposed, then V natural)
//               | Asx[32][128] | Ts[32][128]   = 112 KB
// ---------------------------------------------------------------------------
#define TN 32
#define TM 128

__device__ __forceinline__ float tanh_fast(float x) {
    asm("tanh.approx.f32 %0, %0;" : "+f"(x));
    return x;
}

__global__ void __launch_bounds__(128)
attn_kernel(const float* __restrict__ Aadj)
{
    extern __shared__ float smem[];
    float* Qt  = smem;                       // [d][r]  stride 32
    float* Kb  = Qt + 128 * 32;              // [d][c] (K) / [m][d] (V), stride 128
    float* Asx = Kb + 128 * 128;             // [r][c]  stride 128
    float* Ts  = Asx + 32 * 128;             // [r][c]  stride 128

    int b  = blockIdx.y;
    int n0 = blockIdx.x * TN;
    int t  = threadIdx.x;
    int ty = t >> 4;          // 0..7  -> rows ty*4..ty*4+3
    int tx = t & 15;          // 0..15 -> cols {4tx..4tx+3} U {64+4tx..64+4tx+3}

    const float* Hxb = g_Hx + (long)b * NN * DD;
    const float* Ab  = Aadj + (long)b * NN * NN;

    // Load Q transposed: Qt[d][r]
    {
        int r = t & 31, dgb = t >> 5;
        #pragma unroll
        for (int i = 0; i < 8; i++) {
            int d4 = (dgb + 4 * i) * 4;
            float4 v = *reinterpret_cast<const float4*>(Hxb + (long)(n0 + r) * DD + d4);
            Qt[(d4 + 0) * 32 + r] = v.x; Qt[(d4 + 1) * 32 + r] = v.y;
            Qt[(d4 + 2) * 32 + r] = v.z; Qt[(d4 + 3) * 32 + r] = v.w;
        }
    }

    float hacc[4][8] = {};   // persistent Hout accumulators

    for (int m0 = 0; m0 < NN; m0 += TM) {
        float tacc[4][8] = {};

        for (int h = 0; h < HH; h++) {
            __syncthreads();  // prior readers of Kb/Asx/Ts done
            if (h == 0) {
                #pragma unroll
                for (int i = 0; i < 32; i++)
                    Asx[i * 128 + t] = Ab[(long)(n0 + i) * NN + m0 + t];
            }
            // Load Kh tile transposed: Kb[d][c], thread owns column c=t
            {
                const float* Khp = g_Kh + ((long)h * BB + b) * (long)NN * DD + (long)m0 * DD;
                const float* row = Khp + (long)t * DD;
                #pragma unroll
                for (int i = 0; i < 32; i++) {
                    float4 v = *reinterpret_cast<const float4*>(row + i * 4);
                    Kb[(i * 4 + 0) * 128 + t] = v.x; Kb[(i * 4 + 1) * 128 + t] = v.y;
                    Kb[(i * 4 + 2) * 128 + t] = v.z; Kb[(i * 4 + 3) * 128 + t] = v.w;
                }
            }
            __syncthreads();

            float sacc[4][8] = {};
            #pragma unroll 8
            for (int d = 0; d < 128; d++) {
                float4 qa = *reinterpret_cast<const float4*>(&Qt[d * 32 + ty * 4]);
                float4 k0 = *reinterpret_cast<const float4*>(&Kb[d * 128 + tx * 4]);
                float4 k1 = *reinterpret_cast<const float4*>(&Kb[d * 128 + 64 + tx * 4]);
                float qv[4] = {qa.x, qa.y, qa.z, qa.w};
                float kv[8] = {k0.x, k0.y, k0.z, k0.w, k1.x, k1.y, k1.z, k1.w};
                #pragma unroll
                for (int i = 0; i < 4; i++)
                    #pragma unroll
                    for (int j = 0; j < 8; j++)
                        sacc[i][j] = fmaf(qv[i], kv[j], sacc[i][j]);
            }
            #pragma unroll
            for (int i = 0; i < 4; i++) {
                int r = ty * 4 + i;
                #pragma unroll
                for (int j = 0; j < 8; j++) {
                    int c = (j < 4) ? (tx * 4 + j) : (64 + tx * 4 + (j - 4));
                    tacc[i][j] += tanh_fast(Asx[r * 128 + c] * sacc[i][j]);
                }
            }
        }

        __syncthreads();  // S-phase reads of Kb done; safe to overwrite with V
        #pragma unroll
        for (int i = 0; i < 4; i++) {
            int r = ty * 4 + i;
            #pragma unroll
            for (int j = 0; j < 8; j++) {
                int c = (j < 4) ? (tx * 4 + j) : (64 + tx * 4 + (j - 4));
                Ts[r * 128 + c] = tacc[i][j];
            }
        }
        // Load V tile (natural [m][d]) into Kb
        {
            int c4 = (t & 31) * 4, w = t >> 5;
            #pragma unroll
            for (int i = 0; i < 32; i++) {
                int m = 4 * i + w;
                *reinterpret_cast<float4*>(&Kb[m * 128 + c4]) =
                    *reinterpret_cast<const float4*>(Hxb + (long)(m0 + m) * DD + c4);
            }
        }
        __syncthreads();

        #pragma unroll 4
        for (int m = 0; m < TM; m++) {
            float tv[4];
            #pragma unroll
            for (int i = 0; i < 4; i++) tv[i] = Ts[(ty * 4 + i) * 128 + m];
            float4 v0 = *reinterpret_cast<const float4*>(&Kb[m * 128 + tx * 4]);
            float4 v1 = *reinterpret_cast<const float4*>(&Kb[m * 128 + 64 + tx * 4]);
            float vv[8] = {v0.x, v0.y, v0.z, v0.w, v1.x, v1.y, v1.z, v1.w};
            #pragma unroll
            for (int i = 0; i < 4; i++)
                #pragma unroll
                for (int j = 0; j < 8; j++)
                    hacc[i][j] = fmaf(tv[i], vv[j], hacc[i][j]);
        }
    }

    float* Ho = g_Hout + (long)b * NN * DD;
    #pragma unroll
    for (int i = 0; i < 4; i++) {
        long r = n0 + ty * 4 + i;
        #pragma unroll
        for (int j = 0; j < 8; j++) {
            int c = (j < 4) ? (tx * 4 + j) : (64 + tx * 4 + (j - 4));
            Ho[r * DD + c] = fmaxf(hacc[i][j] * (1.0f / HH), 0.0f);
        }
    }
}

// ---------------------------------------------------------------------------
// Gate: z = sigmoid(Hout@W_u + Xs@W_x + b_u + b_x + update_bias)
//       out = Hout*z + Xs*(1-z).  16 rows/block, 256 threads.
// ---------------------------------------------------------------------------
__global__ void __launch_bounds__(256)
gate_kernel(const float* __restrict__ Wu, const float* __restrict__ bu,
            const float* __restrict__ Wx, const float* __restrict__ bx,
            const float* __restrict__ ub, float* __restrict__ out)
{
    __shared__ float sH[16][128];
    __shared__ float sX[16][128];
    int r0 = blockIdx.x * 16;
    int t  = threadIdx.x;

    for (int i = t; i < 16 * 128; i += 256) {
        int r = i >> 7, c = i & 127;
        sH[r][c] = g_Hout[(long)(r0 + r) * DD + c];
        sX[r][c] = g_Xs  [(long)(r0 + r) * DD + c];
    }
    __syncthreads();

    int ty = t >> 4;        // row 0..15
    int tx = t & 15;        // col block of 8: tx*8..tx*8+7
    float acc[8] = {};
    for (int k = 0; k < 128; k++) {
        float h = sH[ty][k], x = sX[ty][k];
        const float4* wu4 = reinterpret_cast<const float4*>(Wu + k * DD + tx * 8);
        const float4* wx4 = reinterpret_cast<const float4*>(Wx + k * DD + tx * 8);
        float4 u0 = wu4[0], u1 = wu4[1];
        float4 w0 = wx4[0], w1 = wx4[1];
        acc[0] = fmaf(h, u0.x, fmaf(x, w0.x, acc[0]));
        acc[1] = fmaf(h, u0.y, fmaf(x, w0.y, acc[1]));
        acc[2] = fmaf(h, u0.z, fmaf(x, w0.z, acc[2]));
        acc[3] = fmaf(h, u0.w, fmaf(x, w0.w, acc[3]));
        acc[4] = fmaf(h, u1.x, fmaf(x, w1.x, acc[4]));
        acc[5] = fmaf(h, u1.y, fmaf(x, w1.y, acc[5]));
        acc[6] = fmaf(h, u1.z, fmaf(x, w1.z, acc[6]));
        acc[7] = fmaf(h, u1.w, fmaf(x, w1.w, acc[7]));
    }
    #pragma unroll
    for (int j = 0; j < 8; j++) {
        int c = tx * 8 + j;
        float zlin = acc[j] + bu[c] + bx[c] + ub[c];
        float z = 1.0f / (1.0f + expf(-zlin));
        float hv = sH[ty][c], xv = sX[ty][c];
        out[(long)(r0 + ty) * DD + c] = hv * z + xv * (1.0f - z);
    }
}

__global__ void copyA_kernel(const float4* __restrict__ src, float4* __restrict__ dst, long n4)
{
    long i = blockIdx.x * (long)blockDim.x + threadIdx.x;
    long stride = (long)gridDim.x * blockDim.x;
    for (; i < n4; i += stride) dst[i] = src[i];
}

// ---------------------------------------------------------------------------
extern "C" void kernel_launch(void* const* d_in, const int* in_sizes, int n_in,
                              void* d_out, int out_size)
{
    const float* X      = (const float*)d_in[0];
    const float* Aadj   = (const float*)d_in[1];
    const float* kernW  = (const float*)d_in[2];
    const float* bias   = (const float*)d_in[3];
    const float* ubias  = (const float*)d_in[4];
    const float* attn   = (const float*)d_in[5];
    const float* W_skip = (const float*)d_in[6];
    const float* b_skip = (const float*)d_in[7];
    const float* W_u    = (const float*)d_in[8];
    const float* b_u    = (const float*)d_in[9];
    const float* W_x    = (const float*)d_in[10];
    const float* b_x    = (const float*)d_in[11];
    float* out = (float*)d_out;

    float *Hx0, *Hx, *Kh, *Xs;
    cudaGetSymbolAddress((void**)&Hx0, g_Hx0);
    cudaGetSymbolAddress((void**)&Hx,  g_Hx);
    cudaGetSymbolAddress((void**)&Kh,  g_Kh);
    cudaGetSymbolAddress((void**)&Xs,  g_Xs);

    // Stage 1: Hx0 = X @ kernel + bias   [8192,256]@[256,128]
    sgemm_kernel<false><<<dim3(2, 128, 1), 256>>>(
        X, 0, 1, kernW, 0, 1, bias, Hx0, 0, BB * NN, DD, FIN);

    // Stage 2: Hx[b] = A[b] @ Hx0[b]     [2048,2048]@[2048,128] x4
    sgemm_kernel<false><<<dim3(2, 32, 4), 256>>>(
        Aadj, (long)NN * NN, 4, Hx0, (long)NN * DD, 1, nullptr,
        Hx, (long)NN * DD, NN, DD, NN);

    // Stage 3: Kh[h*B+b] = Hx[b] @ attn[h]^T   [2048,128]@[128,128]^T x16
    sgemm_kernel<true><<<dim3(2, 32, 16), 256>>>(
        Hx, (long)NN * DD, 4, attn, (long)DD * DD, 4, nullptr,
        Kh, (long)NN * DD, NN, DD, DD);

    // Stage 5: Xs = X @ W_skip + b_skip
    sgemm_kernel<false><<<dim3(2, 128, 1), 256>>>(
        X, 0, 1, W_skip, 0, 1, b_skip, Xs, 0, BB * NN, DD, FIN);

    // Stage 4: fused masked-tanh attention -> g_Hout
    const int ATTN_SMEM = (128 * 32 + 128 * 128 + 32 * 128 + 32 * 128) * 4; // 112 KB
    cudaFuncSetAttribute(attn_kernel, cudaFuncAttributeMaxDynamicSharedMemorySize, ATTN_SMEM);
    attn_kernel<<<dim3(NN / TN, BB), 128, ATTN_SMEM>>>(Aadj);

    // Stage 6: gated skip -> out[0 : B*N*D]
    gate_kernel<<<BB * NN / 16, 256>>>(W_u, b_u, W_x, b_x, ubias, out);

    // Stage 7: second tuple element: copy A after out
    copyA_kernel<<<1024, 256>>>((const float4*)Aadj,
                                (float4*)(out + (long)BB * NN * DD),
                                (long)BB * NN * NN / 4);
}